// round 15
// baseline (speedup 1.0000x reference)
#include <cuda_runtime.h>
#include <cuda_bf16.h>
#include <cstdint>

#define BATCH 4
#define HW    4096
#define CH    256
#define PROJ_SZ (BATCH * HW * CH)

// ---- device scratch ----
__device__ __nv_bfloat16 g_Pb[5u * PROJ_SZ];                 // projections bf16
__device__ float         g_X3[PROJ_SZ];                      // xw3 fp32
__device__ __nv_bfloat16 g_X3p[PROJ_SZ];                     // invZ2-folded xw3 bf16
__device__ __nv_bfloat16 g_Sx[(size_t)BATCH * HW * HW];
__device__ __nv_bfloat16 g_Sg[(size_t)BATCH * HW * HW];
__device__ __nv_bfloat16 g_V[(size_t)BATCH * HW * HW];
__device__ float g_invZ2[BATCH * HW];
__device__ float g_colpart[2048 * CH];
__device__ float g_colpart2[128 * CH];
__device__ float g_colsum[BATCH * CH];

// ---- mma helpers ----
__device__ __forceinline__ uint32_t cvta_s(const void* p) {
    return (uint32_t)__cvta_generic_to_shared(p);
}
__device__ __forceinline__ void ldsm4(uint32_t* r, uint32_t a) {
    asm volatile("ldmatrix.sync.aligned.m8n8.x4.shared.b16 {%0,%1,%2,%3},[%4];"
                 : "=r"(r[0]), "=r"(r[1]), "=r"(r[2]), "=r"(r[3]) : "r"(a));
}
__device__ __forceinline__ void ldsm4t(uint32_t* r, uint32_t a) {
    asm volatile("ldmatrix.sync.aligned.m8n8.x4.trans.shared.b16 {%0,%1,%2,%3},[%4];"
                 : "=r"(r[0]), "=r"(r[1]), "=r"(r[2]), "=r"(r[3]) : "r"(a));
}
__device__ __forceinline__ void mma16816(float* c, const uint32_t* a, const uint32_t* b) {
    asm volatile("mma.sync.aligned.m16n8k16.row.col.f32.bf16.bf16.f32 "
                 "{%0,%1,%2,%3},{%4,%5,%6,%7},{%8,%9},{%0,%1,%2,%3};"
                 : "+f"(c[0]), "+f"(c[1]), "+f"(c[2]), "+f"(c[3])
                 : "r"(a[0]), "r"(a[1]), "r"(a[2]), "r"(a[3]), "r"(b[0]), "r"(b[1]));
}
__device__ __forceinline__ void cpa16(void* s, const void* g) {
    asm volatile("cp.async.cg.shared.global [%0],[%1],16;" :: "r"(cvta_s(s)), "l"(g));
}
#define CP_COMMIT asm volatile("cp.async.commit_group;")
#define CP_WAIT0  asm volatile("cp.async.wait_group 0;")
#define CP_WAIT2  asm volatile("cp.async.wait_group 2;")

__device__ __forceinline__ uint2 f4b(float4 v) {
    __nv_bfloat162 lo, hi;
    lo.x = __float2bfloat16(v.x); lo.y = __float2bfloat16(v.y);
    hi.x = __float2bfloat16(v.z); hi.y = __float2bfloat16(v.w);
    uint2 r;
    r.x = *(uint32_t*)&lo;
    r.y = *(uint32_t*)&hi;
    return r;
}

// ---------------------------------------------------------------------------
// proj mma (merged z=5) — VERBATIM R14
// ---------------------------------------------------------------------------
__global__ __launch_bounds__(256) void proj_mma_f32(
    const float* __restrict__ x_in, const float* __restrict__ g_in,
    const float* __restrict__ Wx1, const float* __restrict__ bx1,
    const float* __restrict__ Wx2, const float* __restrict__ bx2,
    const float* __restrict__ Wx3, const float* __restrict__ bx3,
    const float* __restrict__ Wg1, const float* __restrict__ bg1,
    const float* __restrict__ Wg2, const float* __restrict__ bg2)
{
    __shared__ __align__(16) __nv_bfloat16 As[2][128][40];
    __shared__ __align__(16) __nv_bfloat16 Ws[2][32][136];
    const int z = blockIdx.z;
    const float* A; const float* W; const float* bias; int wantf32;
    if (z == 0)      { A = x_in; W = Wx1; bias = bx1; wantf32 = 0; }
    else if (z == 1) { A = x_in; W = Wx2; bias = bx2; wantf32 = 0; }
    else if (z == 2) { A = x_in; W = Wx3; bias = bx3; wantf32 = 1; }
    else if (z == 3) { A = g_in; W = Wg1; bias = bg1; wantf32 = 0; }
    else             { A = g_in; W = Wg2; bias = bg2; wantf32 = 0; }

    const int tid = threadIdx.x, lane = tid & 31, wid = tid >> 5;
    const int wm = wid & 1, wn = wid >> 1;
    const int m0 = blockIdx.y * 128, n0 = blockIdx.x * 128;
    __nv_bfloat16* Dst = g_Pb + (size_t)z * PROJ_SZ;

    const int arow = tid >> 1;
    const int ak   = (tid & 1) * 16;
    const int wrow = tid >> 3;
    const int wn16 = (tid & 7) * 16;

    float4 ra0, ra1, ra2, ra3, rw0, rw1, rw2, rw3;
    {
        const float* ap = A + (size_t)(m0 + arow) * CH + ak;
        ra0 = *(const float4*)(ap + 0);  ra1 = *(const float4*)(ap + 4);
        ra2 = *(const float4*)(ap + 8);  ra3 = *(const float4*)(ap + 12);
        const float* wp = W + (size_t)wrow * CH + n0 + wn16;
        rw0 = *(const float4*)(wp + 0);  rw1 = *(const float4*)(wp + 4);
        rw2 = *(const float4*)(wp + 8);  rw3 = *(const float4*)(wp + 12);
    }
    *(uint2*)&As[0][arow][ak + 0]  = f4b(ra0);
    *(uint2*)&As[0][arow][ak + 4]  = f4b(ra1);
    *(uint2*)&As[0][arow][ak + 8]  = f4b(ra2);
    *(uint2*)&As[0][arow][ak + 12] = f4b(ra3);
    *(uint2*)&Ws[0][wrow][wn16 + 0]  = f4b(rw0);
    *(uint2*)&Ws[0][wrow][wn16 + 4]  = f4b(rw1);
    *(uint2*)&Ws[0][wrow][wn16 + 8]  = f4b(rw2);
    *(uint2*)&Ws[0][wrow][wn16 + 12] = f4b(rw3);
    __syncthreads();

    float acc[4][4][4] = {};
#pragma unroll 1
    for (int s = 0; s < 8; s++) {
        if (s < 7) {
            const int k0 = (s + 1) * 32;
            const float* ap = A + (size_t)(m0 + arow) * CH + k0 + ak;
            ra0 = *(const float4*)(ap + 0);  ra1 = *(const float4*)(ap + 4);
            ra2 = *(const float4*)(ap + 8);  ra3 = *(const float4*)(ap + 12);
            const float* wp = W + (size_t)(k0 + wrow) * CH + n0 + wn16;
            rw0 = *(const float4*)(wp + 0);  rw1 = *(const float4*)(wp + 4);
            rw2 = *(const float4*)(wp + 8);  rw3 = *(const float4*)(wp + 12);
        }
        const int st = s & 1;
#pragma unroll
        for (int kk = 0; kk < 2; kk++) {
            uint32_t a[4][4], b[4][2];
#pragma unroll
            for (int mf = 0; mf < 4; mf++) {
                const int row = wm * 64 + mf * 16 + (lane & 15);
                const int ko = kk * 16 + (lane >> 4) * 8;
                ldsm4(a[mf], cvta_s(&As[st][row][ko]));
            }
#pragma unroll
            for (int np = 0; np < 2; np++) {
                const int row = kk * 16 + (lane & 7) + ((lane >> 3) & 1) * 8;
                const int col = wn * 32 + np * 16 + (lane >> 4) * 8;
                uint32_t r[4];
                ldsm4t(r, cvta_s(&Ws[st][row][col]));
                b[2 * np][0] = r[0]; b[2 * np][1] = r[1];
                b[2 * np + 1][0] = r[2]; b[2 * np + 1][1] = r[3];
            }
#pragma unroll
            for (int mf = 0; mf < 4; mf++)
#pragma unroll
                for (int nf = 0; nf < 4; nf++) mma16816(acc[mf][nf], a[mf], b[nf]);
        }
        __syncthreads();
        if (s < 7) {
            const int st2 = (s + 1) & 1;
            *(uint2*)&As[st2][arow][ak + 0]  = f4b(ra0);
            *(uint2*)&As[st2][arow][ak + 4]  = f4b(ra1);
            *(uint2*)&As[st2][arow][ak + 8]  = f4b(ra2);
            *(uint2*)&As[st2][arow][ak + 12] = f4b(ra3);
            *(uint2*)&Ws[st2][wrow][wn16 + 0]  = f4b(rw0);
            *(uint2*)&Ws[st2][wrow][wn16 + 4]  = f4b(rw1);
            *(uint2*)&Ws[st2][wrow][wn16 + 8]  = f4b(rw2);
            *(uint2*)&Ws[st2][wrow][wn16 + 12] = f4b(rw3);
            __syncthreads();
        }
    }

    const int mm0 = m0 + wm * 64, nn0 = n0 + wn * 32;
#pragma unroll
    for (int mf = 0; mf < 4; mf++) {
        const int r0 = mm0 + mf * 16 + (lane >> 2);
#pragma unroll
        for (int nf = 0; nf < 4; nf++) {
            const int col = nn0 + nf * 8 + (lane & 3) * 2;
            const float b0 = bias[col], b1 = bias[col + 1];
            const float f0 = acc[mf][nf][0] + b0, f1 = acc[mf][nf][1] + b1;
            const float f2 = acc[mf][nf][2] + b0, f3 = acc[mf][nf][3] + b1;
            __nv_bfloat162 v0, v1;
            v0.x = __float2bfloat16(f0); v0.y = __float2bfloat16(f1);
            v1.x = __float2bfloat16(f2); v1.y = __float2bfloat16(f3);
            *(__nv_bfloat162*)&Dst[(size_t)r0 * CH + col] = v0;
            *(__nv_bfloat162*)&Dst[(size_t)(r0 + 8) * CH + col] = v1;
            if (wantf32) {
                float2 w0; w0.x = f0; w0.y = f1;
                float2 w1; w1.x = f2; w1.y = f3;
                *(float2*)&g_X3[(size_t)r0 * CH + col] = w0;
                *(float2*)&g_X3[(size_t)(r0 + 8) * CH + col] = w1;
            }
        }
    }
}

// ---------------------------------------------------------------------------
// score_ms — VERBATIM R14 (4-stage cp.async pipeline, merged launch)
// ---------------------------------------------------------------------------
#define SC_TILE 5120   // 128 rows * 40 elems per stage

__global__ __launch_bounds__(256) void score_ms() {
    extern __shared__ __align__(16) __nv_bfloat16 sm[];
    __nv_bfloat16* Asm = sm;
    __nv_bfloat16* Bsm = sm + 4 * SC_TILE;
    const int tid = threadIdx.x, lane = tid & 31, wid = tid >> 5;
    const int wm = wid & 1, wn = wid >> 1;
    const int lrow = tid >> 1, lch = (tid & 1) * 2;
    const int z = blockIdx.z, bat = z >> 1, branch = z & 1;
    const __nv_bfloat16* A  = g_Pb + (size_t)(branch ? 4 : 1) * PROJ_SZ
                              + (size_t)bat * HW * CH + (size_t)blockIdx.y * 128 * CH;
    const __nv_bfloat16* Bm = g_Pb + (size_t)(branch ? 3 : 0) * PROJ_SZ
                              + (size_t)bat * HW * CH + (size_t)blockIdx.x * 128 * CH;
    __nv_bfloat16* Dst = (branch ? g_Sg : g_Sx) + (size_t)bat * HW * HW;

#pragma unroll
    for (int s = 0; s < 3; s++) {
        const int k0 = s * 32;
        __nv_bfloat16* Ad = Asm + s * SC_TILE;
        __nv_bfloat16* Bd = Bsm + s * SC_TILE;
#pragma unroll
        for (int q = 0; q < 2; q++) {
            cpa16(&Ad[lrow * 40 + (lch + q) * 8], A + (size_t)lrow * CH + k0 + (lch + q) * 8);
            cpa16(&Bd[lrow * 40 + (lch + q) * 8], Bm + (size_t)lrow * CH + k0 + (lch + q) * 8);
        }
        CP_COMMIT;
    }

    float acc[4][4][4] = {};
#pragma unroll 1
    for (int s = 0; s < 8; s++) {
        CP_WAIT2;
        __syncthreads();
        const int st = s & 3;
        const __nv_bfloat16* Ap = Asm + st * SC_TILE;
        const __nv_bfloat16* Bp = Bsm + st * SC_TILE;
#pragma unroll
        for (int kk = 0; kk < 2; kk++) {
            uint32_t a[4][4], b[4][2];
#pragma unroll
            for (int mf = 0; mf < 4; mf++) {
                const int row = wm * 64 + mf * 16 + (lane & 15);
                const int ko = kk * 16 + (lane >> 4) * 8;
                ldsm4(a[mf], cvta_s(&Ap[row * 40 + ko]));
            }
#pragma unroll
            for (int np = 0; np < 2; np++) {
                const int row = wn * 32 + np * 16 + (lane & 7) + (lane >> 4) * 8;
                const int ko = kk * 16 + ((lane >> 3) & 1) * 8;
                uint32_t r[4];
                ldsm4(r, cvta_s(&Bp[row * 40 + ko]));
                b[2 * np][0] = r[0]; b[2 * np][1] = r[1];
                b[2 * np + 1][0] = r[2]; b[2 * np + 1][1] = r[3];
            }
#pragma unroll
            for (int mf = 0; mf < 4; mf++)
#pragma unroll
                for (int nf = 0; nf < 4; nf++) mma16816(acc[mf][nf], a[mf], b[nf]);
        }
        if (s < 5) {
            const int k0 = (s + 3) * 32, st2 = (s + 3) & 3;
            __nv_bfloat16* Ad = Asm + st2 * SC_TILE;
            __nv_bfloat16* Bd = Bsm + st2 * SC_TILE;
#pragma unroll
            for (int q = 0; q < 2; q++) {
                cpa16(&Ad[lrow * 40 + (lch + q) * 8],
                      A + (size_t)lrow * CH + k0 + (lch + q) * 8);
                cpa16(&Bd[lrow * 40 + (lch + q) * 8],
                      Bm + (size_t)lrow * CH + k0 + (lch + q) * 8);
            }
        }
        CP_COMMIT;
    }

    const int m0 = blockIdx.y * 128 + wm * 64, n0 = blockIdx.x * 128 + wn * 32;
#pragma unroll
    for (int mf = 0; mf < 4; mf++) {
        const int r0 = m0 + mf * 16 + (lane >> 2);
#pragma unroll
        for (int nf = 0; nf < 4; nf++) {
            const int col = n0 + nf * 8 + (lane & 3) * 2;
            __nv_bfloat162 v0, v1;
            v0.x = __float2bfloat16(acc[mf][nf][0]); v0.y = __float2bfloat16(acc[mf][nf][1]);
            v1.x = __float2bfloat16(acc[mf][nf][2]); v1.y = __float2bfloat16(acc[mf][nf][3]);
            *(__nv_bfloat162*)&Dst[(size_t)r0 * HW + col] = v0;
            *(__nv_bfloat162*)&Dst[(size_t)(r0 + 8) * HW + col] = v1;
        }
    }
}
#define SC_SMEM_BYTES (8 * SC_TILE * 2)   // 81920

// ---------------------------------------------------------------------------
// row stats — 512 threads (halved serial chain vs R14)
// ---------------------------------------------------------------------------
__device__ __forceinline__ float blk_sum512(float v, float* red) {
    int tid = threadIdx.x;
    red[tid] = v; __syncthreads();
    for (int s = 256; s > 0; s >>= 1) {
        if (tid < s) red[tid] += red[tid + s];
        __syncthreads();
    }
    float r = red[0]; __syncthreads();
    return r;
}

__global__ __launch_bounds__(512) void row_stats_kernel() {
    __shared__ float prod[HW];
    __shared__ float red[512];
    const int row = blockIdx.x;
    const int tid = threadIdx.x;
    const __nv_bfloat16* px = g_Sx + (size_t)row * HW;
    const __nv_bfloat16* pg = g_Sg + (size_t)row * HW;

    float s1 = 0.f, s2 = 0.f;
    for (int t = tid; t < HW / 4; t += 512) {
        __nv_bfloat162 x0 = *(const __nv_bfloat162*)&px[t * 4];
        __nv_bfloat162 x1 = *(const __nv_bfloat162*)&px[t * 4 + 2];
        __nv_bfloat162 g0 = *(const __nv_bfloat162*)&pg[t * 4];
        __nv_bfloat162 g1 = *(const __nv_bfloat162*)&pg[t * 4 + 2];
        const float ex0 = __expf(__bfloat162float(x0.x));
        const float ex1 = __expf(__bfloat162float(x0.y));
        const float ex2 = __expf(__bfloat162float(x1.x));
        const float ex3 = __expf(__bfloat162float(x1.y));
        const float eg0 = __expf(__bfloat162float(g0.x));
        const float eg1 = __expf(__bfloat162float(g0.y));
        const float eg2 = __expf(__bfloat162float(g1.x));
        const float eg3 = __expf(__bfloat162float(g1.y));
        s1 += ex0 + ex1 + ex2 + ex3;
        s2 += eg0 + eg1 + eg2 + eg3;
        prod[t * 4 + 0] = ex0 * eg0;
        prod[t * 4 + 1] = ex1 * eg1;
        prod[t * 4 + 2] = ex2 * eg2;
        prod[t * 4 + 3] = ex3 * eg3;
    }
    __syncthreads();
    const float Zx = blk_sum512(s1, red);
    const float Zg = blk_sum512(s2, red);
    const float invZZ = 1.f / (Zx * Zg);

    __nv_bfloat16* vo = g_V + (size_t)row * HW;
    float s = 0.f;
    for (int t = tid; t < HW; t += 512) {
        const float p = prod[t] * invZZ;
        const float vv = p * (1.f + p * (0.5f + p * (0.16666667f
                         + p * (0.04166667f + p * 0.00833333f))));
        s += vv;
        vo[t] = __float2bfloat16(vv);
    }
    const float Z2 = (float)HW + blk_sum512(s, red);
    if (tid == 0) g_invZ2[row] = 1.f / Z2;
}

// ---------------------------------------------------------------------------
// fold + colsum — VERBATIM R14
// ---------------------------------------------------------------------------
__global__ void fold_kernel() {
    const int blk = blockIdx.x;
    const int bat = blk >> 9;
    const int i0 = (blk & 511) * 8;
    const int c = threadIdx.x;
    const float* X = g_X3 + ((size_t)bat * HW + i0) * CH;
    __nv_bfloat16* P = g_X3p + ((size_t)bat * HW + i0) * CH;
    const float* iz = g_invZ2 + bat * HW + i0;
    float s = 0.f;
#pragma unroll
    for (int r = 0; r < 8; r++) {
        const float val = X[(size_t)r * CH + c] * iz[r];
        s += val;
        P[(size_t)r * CH + c] = __float2bfloat16(val);
    }
    g_colpart[blk * CH + c] = s;
}
__global__ void colsum_stage1() {
    const int blk = blockIdx.x;
    const int c = threadIdx.x;
    float s = 0.f;
#pragma unroll 4
    for (int k = 0; k < 16; k++) s += g_colpart[(blk * 16 + k) * CH + c];
    g_colpart2[blk * CH + c] = s;
}
__global__ void colsum_reduce() {
    const int bat = blockIdx.x, c = threadIdx.x;
    float s = 0.f;
#pragma unroll
    for (int k = 0; k < 32; k++) s += g_colpart2[(bat * 32 + k) * CH + c];
    g_colsum[bat * CH + c] = s;
}

// ---------------------------------------------------------------------------
// out_ms64: j-tile 64 x full CH=256, V read ONCE. 4-stage cp.async ring.
// grid (64, 4): x = j-tile, y = bat. Warps 2(j) x 4(c); warp 32x64.
// smem/stage: V 32x72 + X 32x264 (elements); 4 stages = 86016 B.
// ---------------------------------------------------------------------------
#define VT_E 2304   // 32*72
#define XT_E 8448   // 32*264

__global__ __launch_bounds__(256) void out_ms64(const float* __restrict__ x_in,
                                                float* __restrict__ out) {
    extern __shared__ __align__(16) __nv_bfloat16 osm[];
    __nv_bfloat16* Vsm = osm;
    __nv_bfloat16* Xsm = osm + 4 * VT_E;
    __shared__ float cs_s[CH];
    const int bat = blockIdx.y;
    const int j0 = blockIdx.x * 64;
    const __nv_bfloat16* V = g_V + (size_t)bat * HW * HW;      // [i][j]
    const __nv_bfloat16* X = g_X3p + (size_t)bat * HW * CH;    // [i][c]
    const int tid = threadIdx.x, lane = tid & 31, wid = tid >> 5;
    const int wm = wid & 1, wn = wid >> 1;
    const int vrow = tid >> 3;          // 0..31
    const int vcb = tid & 7;            // V: 8 chunks of 8 per row
    const int xcb = (tid & 7) * 4;      // X: 4 chunks each

    cs_s[tid] = g_colsum[bat * CH + tid];

    // prefetch stages 0..2
#pragma unroll
    for (int s = 0; s < 3; s++) {
        const int i0 = s * 32;
        __nv_bfloat16* Vd = Vsm + s * VT_E;
        __nv_bfloat16* Xd = Xsm + s * XT_E;
        cpa16(&Vd[vrow * 72 + vcb * 8], V + (size_t)(i0 + vrow) * HW + j0 + vcb * 8);
#pragma unroll
        for (int q = 0; q < 4; q++)
            cpa16(&Xd[vrow * 264 + (xcb + q) * 8],
                  X + (size_t)(i0 + vrow) * CH + (xcb + q) * 8);
        CP_COMMIT;
    }

    float acc[2][8][4] = {};
#pragma unroll 1
    for (int s = 0; s < 128; s++) {
        CP_WAIT2;
        __syncthreads();
        const int st = s & 3;
        const __nv_bfloat16* Vp = Vsm + st * VT_E;
        const __nv_bfloat16* Xp = Xsm + st * XT_E;
#pragma unroll
        for (int kk = 0; kk < 2; kk++) {
            uint32_t a[2][4], b[8][2];
#pragma unroll
            for (int mf = 0; mf < 2; mf++) {
                const int row = kk * 16 + (lane & 7) + (lane >> 4) * 8;
                const int col = wm * 32 + mf * 16 + ((lane >> 3) & 1) * 8;
                ldsm4t(a[mf], cvta_s(&Vp[row * 72 + col]));
            }
#pragma unroll
            for (int np = 0; np < 4; np++) {
                const int row = kk * 16 + (lane & 7) + ((lane >> 3) & 1) * 8;
                const int col = wn * 64 + np * 16 + (lane >> 4) * 8;
                uint32_t r[4];
                ldsm4t(r, cvta_s(&Xp[row * 264 + col]));
                b[2 * np][0] = r[0]; b[2 * np][1] = r[1];
                b[2 * np + 1][0] = r[2]; b[2 * np + 1][1] = r[3];
            }
#pragma unroll
            for (int mf = 0; mf < 2; mf++)
#pragma unroll
                for (int nf = 0; nf < 8; nf++) mma16816(acc[mf][nf], a[mf], b[nf]);
        }
        if (s < 125) {
            const int i0 = (s + 3) * 32, st2 = (s + 3) & 3;
            __nv_bfloat16* Vd = Vsm + st2 * VT_E;
            __nv_bfloat16* Xd = Xsm + st2 * XT_E;
            cpa16(&Vd[vrow * 72 + vcb * 8], V + (size_t)(i0 + vrow) * HW + j0 + vcb * 8);
#pragma unroll
            for (int q = 0; q < 4; q++)
                cpa16(&Xd[vrow * 264 + (xcb + q) * 8],
                      X + (size_t)(i0 + vrow) * CH + (xcb + q) * 8);
        }
        CP_COMMIT;
    }

#pragma unroll
    for (int mf = 0; mf < 2; mf++) {
        const int j = j0 + wm * 32 + mf * 16 + (lane >> 2);
#pragma unroll
        for (int nf = 0; nf < 8; nf++) {
            const int cc = wn * 64 + nf * 8 + (lane & 3) * 2;
            const size_t b0 = ((size_t)bat * HW + j) * CH + cc;
            float2 xv = *(const float2*)&x_in[b0];
            float2 o;
            o.x = acc[mf][nf][0] + xv.x + cs_s[cc];
            o.y = acc[mf][nf][1] + xv.y + cs_s[cc + 1];
            *(float2*)&out[b0] = o;
            const size_t b1 = b0 + 8u * CH;
            float2 xv2 = *(const float2*)&x_in[b1];
            float2 o2;
            o2.x = acc[mf][nf][2] + xv2.x + cs_s[cc];
            o2.y = acc[mf][nf][3] + xv2.y + cs_s[cc + 1];
            *(float2*)&out[b1] = o2;
        }
    }
}
#define OT64_SMEM_BYTES ((4 * VT_E + 4 * XT_E) * 2)   // 86016

// ---------------------------------------------------------------------------
extern "C" void kernel_launch(void* const* d_in, const int* in_sizes, int n_in,
                              void* d_out, int out_size) {
    (void)in_sizes; (void)n_in; (void)out_size;
    const float* x   = (const float*)d_in[0];
    const float* g   = (const float*)d_in[1];
    float* out = (float*)d_out;

    dim3 pg(CH / 128, (BATCH * HW) / 128, 5);
    proj_mma_f32<<<pg, 256>>>(x, g,
        (const float*)d_in[2],  (const float*)d_in[3],
        (const float*)d_in[4],  (const float*)d_in[5],
        (const float*)d_in[6],  (const float*)d_in[7],
        (const float*)d_in[8],  (const float*)d_in[9],
        (const float*)d_in[10], (const float*)d_in[11]);

    cudaFuncSetAttribute(score_ms, cudaFuncAttributeMaxDynamicSharedMemorySize,
                         SC_SMEM_BYTES);
    score_ms<<<dim3(32, 32, 8), 256, SC_SMEM_BYTES>>>();

    row_stats_kernel<<<BATCH * HW, 512>>>();
    fold_kernel<<<2048, 256>>>();
    colsum_stage1<<<128, 256>>>();
    colsum_reduce<<<BATCH, 256>>>();

    cudaFuncSetAttribute(out_ms64, cudaFuncAttributeMaxDynamicSharedMemorySize,
                         OT64_SMEM_BYTES);
    out_ms64<<<dim3(HW / 64, BATCH), 256, OT64_SMEM_BYTES>>>(x, out);
}

// round 16
// speedup vs baseline: 1.0587x; 1.0587x over previous
#include <cuda_runtime.h>
#include <cuda_bf16.h>
#include <cstdint>

#define BATCH 4
#define HW    4096
#define CH    256
#define PROJ_SZ (BATCH * HW * CH)

// ---- device scratch ----
__device__ __nv_bfloat16 g_Pb[5u * PROJ_SZ];                 // projections bf16
__device__ float         g_X3[PROJ_SZ];                      // xw3 fp32
__device__ __nv_bfloat16 g_X3p[PROJ_SZ];                     // invZ2-folded xw3 bf16
__device__ __nv_bfloat16 g_Sx[(size_t)BATCH * HW * HW];
__device__ __nv_bfloat16 g_Sg[(size_t)BATCH * HW * HW];
__device__ __nv_bfloat16 g_V[(size_t)BATCH * HW * HW];
__device__ float g_invZ2[BATCH * HW];
__device__ float g_colpart[2048 * CH];
__device__ float g_colpart2[128 * CH];
__device__ float g_colsum[BATCH * CH];

// ---- mma helpers ----
__device__ __forceinline__ uint32_t cvta_s(const void* p) {
    return (uint32_t)__cvta_generic_to_shared(p);
}
__device__ __forceinline__ void ldsm4(uint32_t* r, uint32_t a) {
    asm volatile("ldmatrix.sync.aligned.m8n8.x4.shared.b16 {%0,%1,%2,%3},[%4];"
                 : "=r"(r[0]), "=r"(r[1]), "=r"(r[2]), "=r"(r[3]) : "r"(a));
}
__device__ __forceinline__ void ldsm4t(uint32_t* r, uint32_t a) {
    asm volatile("ldmatrix.sync.aligned.m8n8.x4.trans.shared.b16 {%0,%1,%2,%3},[%4];"
                 : "=r"(r[0]), "=r"(r[1]), "=r"(r[2]), "=r"(r[3]) : "r"(a));
}
__device__ __forceinline__ void mma16816(float* c, const uint32_t* a, const uint32_t* b) {
    asm volatile("mma.sync.aligned.m16n8k16.row.col.f32.bf16.bf16.f32 "
                 "{%0,%1,%2,%3},{%4,%5,%6,%7},{%8,%9},{%0,%1,%2,%3};"
                 : "+f"(c[0]), "+f"(c[1]), "+f"(c[2]), "+f"(c[3])
                 : "r"(a[0]), "r"(a[1]), "r"(a[2]), "r"(a[3]), "r"(b[0]), "r"(b[1]));
}
__device__ __forceinline__ void cpa16(void* s, const void* g) {
    asm volatile("cp.async.cg.shared.global [%0],[%1],16;" :: "r"(cvta_s(s)), "l"(g));
}
#define CP_COMMIT asm volatile("cp.async.commit_group;")
#define CP_WAIT0  asm volatile("cp.async.wait_group 0;")
#define CP_WAIT2  asm volatile("cp.async.wait_group 2;")

__device__ __forceinline__ uint2 f4b(float4 v) {
    __nv_bfloat162 lo, hi;
    lo.x = __float2bfloat16(v.x); lo.y = __float2bfloat16(v.y);
    hi.x = __float2bfloat16(v.z); hi.y = __float2bfloat16(v.w);
    uint2 r;
    r.x = *(uint32_t*)&lo;
    r.y = *(uint32_t*)&hi;
    return r;
}

// ---------------------------------------------------------------------------
// proj mma (merged z=5) — VERBATIM R14
// ---------------------------------------------------------------------------
__global__ __launch_bounds__(256) void proj_mma_f32(
    const float* __restrict__ x_in, const float* __restrict__ g_in,
    const float* __restrict__ Wx1, const float* __restrict__ bx1,
    const float* __restrict__ Wx2, const float* __restrict__ bx2,
    const float* __restrict__ Wx3, const float* __restrict__ bx3,
    const float* __restrict__ Wg1, const float* __restrict__ bg1,
    const float* __restrict__ Wg2, const float* __restrict__ bg2)
{
    __shared__ __align__(16) __nv_bfloat16 As[2][128][40];
    __shared__ __align__(16) __nv_bfloat16 Ws[2][32][136];
    const int z = blockIdx.z;
    const float* A; const float* W; const float* bias; int wantf32;
    if (z == 0)      { A = x_in; W = Wx1; bias = bx1; wantf32 = 0; }
    else if (z == 1) { A = x_in; W = Wx2; bias = bx2; wantf32 = 0; }
    else if (z == 2) { A = x_in; W = Wx3; bias = bx3; wantf32 = 1; }
    else if (z == 3) { A = g_in; W = Wg1; bias = bg1; wantf32 = 0; }
    else             { A = g_in; W = Wg2; bias = bg2; wantf32 = 0; }

    const int tid = threadIdx.x, lane = tid & 31, wid = tid >> 5;
    const int wm = wid & 1, wn = wid >> 1;
    const int m0 = blockIdx.y * 128, n0 = blockIdx.x * 128;
    __nv_bfloat16* Dst = g_Pb + (size_t)z * PROJ_SZ;

    const int arow = tid >> 1;
    const int ak   = (tid & 1) * 16;
    const int wrow = tid >> 3;
    const int wn16 = (tid & 7) * 16;

    float4 ra0, ra1, ra2, ra3, rw0, rw1, rw2, rw3;
    {
        const float* ap = A + (size_t)(m0 + arow) * CH + ak;
        ra0 = *(const float4*)(ap + 0);  ra1 = *(const float4*)(ap + 4);
        ra2 = *(const float4*)(ap + 8);  ra3 = *(const float4*)(ap + 12);
        const float* wp = W + (size_t)wrow * CH + n0 + wn16;
        rw0 = *(const float4*)(wp + 0);  rw1 = *(const float4*)(wp + 4);
        rw2 = *(const float4*)(wp + 8);  rw3 = *(const float4*)(wp + 12);
    }
    *(uint2*)&As[0][arow][ak + 0]  = f4b(ra0);
    *(uint2*)&As[0][arow][ak + 4]  = f4b(ra1);
    *(uint2*)&As[0][arow][ak + 8]  = f4b(ra2);
    *(uint2*)&As[0][arow][ak + 12] = f4b(ra3);
    *(uint2*)&Ws[0][wrow][wn16 + 0]  = f4b(rw0);
    *(uint2*)&Ws[0][wrow][wn16 + 4]  = f4b(rw1);
    *(uint2*)&Ws[0][wrow][wn16 + 8]  = f4b(rw2);
    *(uint2*)&Ws[0][wrow][wn16 + 12] = f4b(rw3);
    __syncthreads();

    float acc[4][4][4] = {};
#pragma unroll 1
    for (int s = 0; s < 8; s++) {
        if (s < 7) {
            const int k0 = (s + 1) * 32;
            const float* ap = A + (size_t)(m0 + arow) * CH + k0 + ak;
            ra0 = *(const float4*)(ap + 0);  ra1 = *(const float4*)(ap + 4);
            ra2 = *(const float4*)(ap + 8);  ra3 = *(const float4*)(ap + 12);
            const float* wp = W + (size_t)(k0 + wrow) * CH + n0 + wn16;
            rw0 = *(const float4*)(wp + 0);  rw1 = *(const float4*)(wp + 4);
            rw2 = *(const float4*)(wp + 8);  rw3 = *(const float4*)(wp + 12);
        }
        const int st = s & 1;
#pragma unroll
        for (int kk = 0; kk < 2; kk++) {
            uint32_t a[4][4], b[4][2];
#pragma unroll
            for (int mf = 0; mf < 4; mf++) {
                const int row = wm * 64 + mf * 16 + (lane & 15);
                const int ko = kk * 16 + (lane >> 4) * 8;
                ldsm4(a[mf], cvta_s(&As[st][row][ko]));
            }
#pragma unroll
            for (int np = 0; np < 2; np++) {
                const int row = kk * 16 + (lane & 7) + ((lane >> 3) & 1) * 8;
                const int col = wn * 32 + np * 16 + (lane >> 4) * 8;
                uint32_t r[4];
                ldsm4t(r, cvta_s(&Ws[st][row][col]));
                b[2 * np][0] = r[0]; b[2 * np][1] = r[1];
                b[2 * np + 1][0] = r[2]; b[2 * np + 1][1] = r[3];
            }
#pragma unroll
            for (int mf = 0; mf < 4; mf++)
#pragma unroll
                for (int nf = 0; nf < 4; nf++) mma16816(acc[mf][nf], a[mf], b[nf]);
        }
        __syncthreads();
        if (s < 7) {
            const int st2 = (s + 1) & 1;
            *(uint2*)&As[st2][arow][ak + 0]  = f4b(ra0);
            *(uint2*)&As[st2][arow][ak + 4]  = f4b(ra1);
            *(uint2*)&As[st2][arow][ak + 8]  = f4b(ra2);
            *(uint2*)&As[st2][arow][ak + 12] = f4b(ra3);
            *(uint2*)&Ws[st2][wrow][wn16 + 0]  = f4b(rw0);
            *(uint2*)&Ws[st2][wrow][wn16 + 4]  = f4b(rw1);
            *(uint2*)&Ws[st2][wrow][wn16 + 8]  = f4b(rw2);
            *(uint2*)&Ws[st2][wrow][wn16 + 12] = f4b(rw3);
            __syncthreads();
        }
    }

    const int mm0 = m0 + wm * 64, nn0 = n0 + wn * 32;
#pragma unroll
    for (int mf = 0; mf < 4; mf++) {
        const int r0 = mm0 + mf * 16 + (lane >> 2);
#pragma unroll
        for (int nf = 0; nf < 4; nf++) {
            const int col = nn0 + nf * 8 + (lane & 3) * 2;
            const float b0 = bias[col], b1 = bias[col + 1];
            const float f0 = acc[mf][nf][0] + b0, f1 = acc[mf][nf][1] + b1;
            const float f2 = acc[mf][nf][2] + b0, f3 = acc[mf][nf][3] + b1;
            __nv_bfloat162 v0, v1;
            v0.x = __float2bfloat16(f0); v0.y = __float2bfloat16(f1);
            v1.x = __float2bfloat16(f2); v1.y = __float2bfloat16(f3);
            *(__nv_bfloat162*)&Dst[(size_t)r0 * CH + col] = v0;
            *(__nv_bfloat162*)&Dst[(size_t)(r0 + 8) * CH + col] = v1;
            if (wantf32) {
                float2 w0; w0.x = f0; w0.y = f1;
                float2 w1; w1.x = f2; w1.y = f3;
                *(float2*)&g_X3[(size_t)r0 * CH + col] = w0;
                *(float2*)&g_X3[(size_t)(r0 + 8) * CH + col] = w1;
            }
        }
    }
}

// ---------------------------------------------------------------------------
// score_ms — VERBATIM R14 (4-stage cp.async pipeline, merged launch)
// ---------------------------------------------------------------------------
#define SC_TILE 5120   // 128 rows * 40 elems per stage

__global__ __launch_bounds__(256) void score_ms() {
    extern __shared__ __align__(16) __nv_bfloat16 sm[];
    __nv_bfloat16* Asm = sm;
    __nv_bfloat16* Bsm = sm + 4 * SC_TILE;
    const int tid = threadIdx.x, lane = tid & 31, wid = tid >> 5;
    const int wm = wid & 1, wn = wid >> 1;
    const int lrow = tid >> 1, lch = (tid & 1) * 2;
    const int z = blockIdx.z, bat = z >> 1, branch = z & 1;
    const __nv_bfloat16* A  = g_Pb + (size_t)(branch ? 4 : 1) * PROJ_SZ
                              + (size_t)bat * HW * CH + (size_t)blockIdx.y * 128 * CH;
    const __nv_bfloat16* Bm = g_Pb + (size_t)(branch ? 3 : 0) * PROJ_SZ
                              + (size_t)bat * HW * CH + (size_t)blockIdx.x * 128 * CH;
    __nv_bfloat16* Dst = (branch ? g_Sg : g_Sx) + (size_t)bat * HW * HW;

#pragma unroll
    for (int s = 0; s < 3; s++) {
        const int k0 = s * 32;
        __nv_bfloat16* Ad = Asm + s * SC_TILE;
        __nv_bfloat16* Bd = Bsm + s * SC_TILE;
#pragma unroll
        for (int q = 0; q < 2; q++) {
            cpa16(&Ad[lrow * 40 + (lch + q) * 8], A + (size_t)lrow * CH + k0 + (lch + q) * 8);
            cpa16(&Bd[lrow * 40 + (lch + q) * 8], Bm + (size_t)lrow * CH + k0 + (lch + q) * 8);
        }
        CP_COMMIT;
    }

    float acc[4][4][4] = {};
#pragma unroll 1
    for (int s = 0; s < 8; s++) {
        CP_WAIT2;
        __syncthreads();
        const int st = s & 3;
        const __nv_bfloat16* Ap = Asm + st * SC_TILE;
        const __nv_bfloat16* Bp = Bsm + st * SC_TILE;
#pragma unroll
        for (int kk = 0; kk < 2; kk++) {
            uint32_t a[4][4], b[4][2];
#pragma unroll
            for (int mf = 0; mf < 4; mf++) {
                const int row = wm * 64 + mf * 16 + (lane & 15);
                const int ko = kk * 16 + (lane >> 4) * 8;
                ldsm4(a[mf], cvta_s(&Ap[row * 40 + ko]));
            }
#pragma unroll
            for (int np = 0; np < 2; np++) {
                const int row = wn * 32 + np * 16 + (lane & 7) + (lane >> 4) * 8;
                const int ko = kk * 16 + ((lane >> 3) & 1) * 8;
                uint32_t r[4];
                ldsm4(r, cvta_s(&Bp[row * 40 + ko]));
                b[2 * np][0] = r[0]; b[2 * np][1] = r[1];
                b[2 * np + 1][0] = r[2]; b[2 * np + 1][1] = r[3];
            }
#pragma unroll
            for (int mf = 0; mf < 4; mf++)
#pragma unroll
                for (int nf = 0; nf < 4; nf++) mma16816(acc[mf][nf], a[mf], b[nf]);
        }
        if (s < 5) {
            const int k0 = (s + 3) * 32, st2 = (s + 3) & 3;
            __nv_bfloat16* Ad = Asm + st2 * SC_TILE;
            __nv_bfloat16* Bd = Bsm + st2 * SC_TILE;
#pragma unroll
            for (int q = 0; q < 2; q++) {
                cpa16(&Ad[lrow * 40 + (lch + q) * 8],
                      A + (size_t)lrow * CH + k0 + (lch + q) * 8);
                cpa16(&Bd[lrow * 40 + (lch + q) * 8],
                      Bm + (size_t)lrow * CH + k0 + (lch + q) * 8);
            }
        }
        CP_COMMIT;
    }

    const int m0 = blockIdx.y * 128 + wm * 64, n0 = blockIdx.x * 128 + wn * 32;
#pragma unroll
    for (int mf = 0; mf < 4; mf++) {
        const int r0 = m0 + mf * 16 + (lane >> 2);
#pragma unroll
        for (int nf = 0; nf < 4; nf++) {
            const int col = n0 + nf * 8 + (lane & 3) * 2;
            __nv_bfloat162 v0, v1;
            v0.x = __float2bfloat16(acc[mf][nf][0]); v0.y = __float2bfloat16(acc[mf][nf][1]);
            v1.x = __float2bfloat16(acc[mf][nf][2]); v1.y = __float2bfloat16(acc[mf][nf][3]);
            *(__nv_bfloat162*)&Dst[(size_t)r0 * HW + col] = v0;
            *(__nv_bfloat162*)&Dst[(size_t)(r0 + 8) * HW + col] = v1;
        }
    }
}
#define SC_SMEM_BYTES (8 * SC_TILE * 2)   // 81920

// ---------------------------------------------------------------------------
// row stats — 512 threads (kept from R15)
// ---------------------------------------------------------------------------
__device__ __forceinline__ float blk_sum512(float v, float* red) {
    int tid = threadIdx.x;
    red[tid] = v; __syncthreads();
    for (int s = 256; s > 0; s >>= 1) {
        if (tid < s) red[tid] += red[tid + s];
        __syncthreads();
    }
    float r = red[0]; __syncthreads();
    return r;
}

__global__ __launch_bounds__(512) void row_stats_kernel() {
    __shared__ float prod[HW];
    __shared__ float red[512];
    const int row = blockIdx.x;
    const int tid = threadIdx.x;
    const __nv_bfloat16* px = g_Sx + (size_t)row * HW;
    const __nv_bfloat16* pg = g_Sg + (size_t)row * HW;

    float s1 = 0.f, s2 = 0.f;
    for (int t = tid; t < HW / 4; t += 512) {
        __nv_bfloat162 x0 = *(const __nv_bfloat162*)&px[t * 4];
        __nv_bfloat162 x1 = *(const __nv_bfloat162*)&px[t * 4 + 2];
        __nv_bfloat162 g0 = *(const __nv_bfloat162*)&pg[t * 4];
        __nv_bfloat162 g1 = *(const __nv_bfloat162*)&pg[t * 4 + 2];
        const float ex0 = __expf(__bfloat162float(x0.x));
        const float ex1 = __expf(__bfloat162float(x0.y));
        const float ex2 = __expf(__bfloat162float(x1.x));
        const float ex3 = __expf(__bfloat162float(x1.y));
        const float eg0 = __expf(__bfloat162float(g0.x));
        const float eg1 = __expf(__bfloat162float(g0.y));
        const float eg2 = __expf(__bfloat162float(g1.x));
        const float eg3 = __expf(__bfloat162float(g1.y));
        s1 += ex0 + ex1 + ex2 + ex3;
        s2 += eg0 + eg1 + eg2 + eg3;
        prod[t * 4 + 0] = ex0 * eg0;
        prod[t * 4 + 1] = ex1 * eg1;
        prod[t * 4 + 2] = ex2 * eg2;
        prod[t * 4 + 3] = ex3 * eg3;
    }
    __syncthreads();
    const float Zx = blk_sum512(s1, red);
    const float Zg = blk_sum512(s2, red);
    const float invZZ = 1.f / (Zx * Zg);

    __nv_bfloat16* vo = g_V + (size_t)row * HW;
    float s = 0.f;
    for (int t = tid; t < HW; t += 512) {
        const float p = prod[t] * invZZ;
        const float vv = p * (1.f + p * (0.5f + p * (0.16666667f
                         + p * (0.04166667f + p * 0.00833333f))));
        s += vv;
        vo[t] = __float2bfloat16(vv);
    }
    const float Z2 = (float)HW + blk_sum512(s, red);
    if (tid == 0) g_invZ2[row] = 1.f / Z2;
}

// ---------------------------------------------------------------------------
// fold + colsum — VERBATIM R14
// ---------------------------------------------------------------------------
__global__ void fold_kernel() {
    const int blk = blockIdx.x;
    const int bat = blk >> 9;
    const int i0 = (blk & 511) * 8;
    const int c = threadIdx.x;
    const float* X = g_X3 + ((size_t)bat * HW + i0) * CH;
    __nv_bfloat16* P = g_X3p + ((size_t)bat * HW + i0) * CH;
    const float* iz = g_invZ2 + bat * HW + i0;
    float s = 0.f;
#pragma unroll
    for (int r = 0; r < 8; r++) {
        const float val = X[(size_t)r * CH + c] * iz[r];
        s += val;
        P[(size_t)r * CH + c] = __float2bfloat16(val);
    }
    g_colpart[blk * CH + c] = s;
}
__global__ void colsum_stage1() {
    const int blk = blockIdx.x;
    const int c = threadIdx.x;
    float s = 0.f;
#pragma unroll 4
    for (int k = 0; k < 16; k++) s += g_colpart[(blk * 16 + k) * CH + c];
    g_colpart2[blk * CH + c] = s;
}
__global__ void colsum_reduce() {
    const int bat = blockIdx.x, c = threadIdx.x;
    float s = 0.f;
#pragma unroll
    for (int k = 0; k < 32; k++) s += g_colpart2[(bat * 32 + k) * CH + c];
    g_colsum[bat * CH + c] = s;
}

// ---------------------------------------------------------------------------
// out_ms — VERBATIM R14 (4-stage cp.async ring, 128x128 tile)
// ---------------------------------------------------------------------------
#define OT_TILE 4352   // 32 * 136

__global__ __launch_bounds__(256) void out_ms(const float* __restrict__ x_in,
                                              float* __restrict__ out) {
    extern __shared__ __align__(16) __nv_bfloat16 osm[];
    __nv_bfloat16* Vsm = osm;
    __nv_bfloat16* Xsm = osm + 4 * OT_TILE;
    __shared__ float cs_s[128];
    const int bat = blockIdx.z;
    const int j0 = blockIdx.y * 128, c0 = blockIdx.x * 128;
    const __nv_bfloat16* V = g_V + (size_t)bat * HW * HW;      // [i][j]
    const __nv_bfloat16* X = g_X3p + (size_t)bat * HW * CH;    // [i][c]
    const int tid = threadIdx.x, lane = tid & 31, wid = tid >> 5;
    const int wm = wid & 1, wn = wid >> 1;
    const int vrow = tid >> 3;          // 0..31
    const int vch = (tid & 7) * 2;

    if (tid < 128) cs_s[tid] = g_colsum[bat * CH + c0 + tid];

    // prefetch stages 0..2
#pragma unroll
    for (int s = 0; s < 3; s++) {
        const int i0 = s * 32;
        __nv_bfloat16* Vd = Vsm + s * OT_TILE;
        __nv_bfloat16* Xd = Xsm + s * OT_TILE;
#pragma unroll
        for (int q = 0; q < 2; q++) {
            cpa16(&Vd[vrow * 136 + (vch + q) * 8],
                  V + (size_t)(i0 + vrow) * HW + j0 + (vch + q) * 8);
            cpa16(&Xd[vrow * 136 + (vch + q) * 8],
                  X + (size_t)(i0 + vrow) * CH + c0 + (vch + q) * 8);
        }
        CP_COMMIT;
    }

    float acc[4][4][4] = {};
#pragma unroll 1
    for (int s = 0; s < 128; s++) {
        CP_WAIT2;
        __syncthreads();
        const int st = s & 3;
        const __nv_bfloat16* Vp = Vsm + st * OT_TILE;
        const __nv_bfloat16* Xp = Xsm + st * OT_TILE;
#pragma unroll
        for (int kk = 0; kk < 2; kk++) {
            uint32_t a[4][4], b[4][2];
#pragma unroll
            for (int mf = 0; mf < 4; mf++) {
                const int row = kk * 16 + (lane & 7) + (lane >> 4) * 8;
                const int col = wm * 64 + mf * 16 + ((lane >> 3) & 1) * 8;
                ldsm4t(a[mf], cvta_s(&Vp[row * 136 + col]));
            }
#pragma unroll
            for (int np = 0; np < 2; np++) {
                const int row = kk * 16 + (lane & 7) + ((lane >> 3) & 1) * 8;
                const int col = wn * 32 + np * 16 + (lane >> 4) * 8;
                uint32_t r[4];
                ldsm4t(r, cvta_s(&Xp[row * 136 + col]));
                b[2 * np][0] = r[0]; b[2 * np][1] = r[1];
                b[2 * np + 1][0] = r[2]; b[2 * np + 1][1] = r[3];
            }
#pragma unroll
            for (int mf = 0; mf < 4; mf++)
#pragma unroll
                for (int nf = 0; nf < 4; nf++) mma16816(acc[mf][nf], a[mf], b[nf]);
        }
        if (s < 125) {
            const int i0 = (s + 3) * 32, st2 = (s + 3) & 3;
            __nv_bfloat16* Vd = Vsm + st2 * OT_TILE;
            __nv_bfloat16* Xd = Xsm + st2 * OT_TILE;
#pragma unroll
            for (int q = 0; q < 2; q++) {
                cpa16(&Vd[vrow * 136 + (vch + q) * 8],
                      V + (size_t)(i0 + vrow) * HW + j0 + (vch + q) * 8);
                cpa16(&Xd[vrow * 136 + (vch + q) * 8],
                      X + (size_t)(i0 + vrow) * CH + c0 + (vch + q) * 8);
            }
        }
        CP_COMMIT;
    }

#pragma unroll
    for (int mf = 0; mf < 4; mf++) {
        const int j = j0 + wm * 64 + mf * 16 + (lane >> 2);
#pragma unroll
        for (int nf = 0; nf < 4; nf++) {
            const int cc = wn * 32 + nf * 8 + (lane & 3) * 2;
            const size_t b0 = ((size_t)bat * HW + j) * CH + c0 + cc;
            float2 xv = *(const float2*)&x_in[b0];
            float2 o;
            o.x = acc[mf][nf][0] + xv.x + cs_s[cc];
            o.y = acc[mf][nf][1] + xv.y + cs_s[cc + 1];
            *(float2*)&out[b0] = o;
            const size_t b1 = ((size_t)bat * HW + j + 8) * CH + c0 + cc;
            float2 xv2 = *(const float2*)&x_in[b1];
            float2 o2;
            o2.x = acc[mf][nf][2] + xv2.x + cs_s[cc];
            o2.y = acc[mf][nf][3] + xv2.y + cs_s[cc + 1];
            *(float2*)&out[b1] = o2;
        }
    }
}
#define OT_SMEM_BYTES (8 * OT_TILE * 2)   // 69632

// ---------------------------------------------------------------------------
extern "C" void kernel_launch(void* const* d_in, const int* in_sizes, int n_in,
                              void* d_out, int out_size) {
    (void)in_sizes; (void)n_in; (void)out_size;
    const float* x   = (const float*)d_in[0];
    const float* g   = (const float*)d_in[1];
    float* out = (float*)d_out;

    dim3 pg(CH / 128, (BATCH * HW) / 128, 5);
    proj_mma_f32<<<pg, 256>>>(x, g,
        (const float*)d_in[2],  (const float*)d_in[3],
        (const float*)d_in[4],  (const float*)d_in[5],
        (const float*)d_in[6],  (const float*)d_in[7],
        (const float*)d_in[8],  (const float*)d_in[9],
        (const float*)d_in[10], (const float*)d_in[11]);

    cudaFuncSetAttribute(score_ms, cudaFuncAttributeMaxDynamicSharedMemorySize,
                         SC_SMEM_BYTES);
    score_ms<<<dim3(32, 32, 8), 256, SC_SMEM_BYTES>>>();

    row_stats_kernel<<<BATCH * HW, 512>>>();
    fold_kernel<<<2048, 256>>>();
    colsum_stage1<<<128, 256>>>();
    colsum_reduce<<<BATCH, 256>>>();

    cudaFuncSetAttribute(out_ms, cudaFuncAttributeMaxDynamicSharedMemorySize,
                         OT_SMEM_BYTES);
    out_ms<<<dim3(CH / 128, HW / 128, BATCH), 256, OT_SMEM_BYTES>>>(x, out);
}

// round 17
// speedup vs baseline: 1.1334x; 1.0705x over previous
#include <cuda_runtime.h>
#include <cuda_bf16.h>
#include <cstdint>

#define BATCH 4
#define HW    4096
#define CH    256
#define PROJ_SZ (BATCH * HW * CH)

// ---- device scratch ----
__device__ __nv_bfloat16 g_Pb[5u * PROJ_SZ];                 // projections bf16
__device__ float         g_X3[PROJ_SZ];                      // xw3 fp32
__device__ __nv_bfloat16 g_X3p[PROJ_SZ];                     // invZ2-folded xw3 bf16
__device__ __nv_bfloat16 g_Ex[(size_t)BATCH * HW * HW];      // exp(Sx) bf16
__device__ __nv_bfloat16 g_Eg[(size_t)BATCH * HW * HW];      // exp(Sg) bf16
__device__ __nv_bfloat16 g_V[(size_t)BATCH * HW * HW];
__device__ float g_invZ2[BATCH * HW];
__device__ float g_colpart[2048 * CH];
__device__ float g_colpart2[128 * CH];
__device__ float g_colsum[BATCH * CH];

// ---- mma helpers ----
__device__ __forceinline__ uint32_t cvta_s(const void* p) {
    return (uint32_t)__cvta_generic_to_shared(p);
}
__device__ __forceinline__ void ldsm4(uint32_t* r, uint32_t a) {
    asm volatile("ldmatrix.sync.aligned.m8n8.x4.shared.b16 {%0,%1,%2,%3},[%4];"
                 : "=r"(r[0]), "=r"(r[1]), "=r"(r[2]), "=r"(r[3]) : "r"(a));
}
__device__ __forceinline__ void ldsm4t(uint32_t* r, uint32_t a) {
    asm volatile("ldmatrix.sync.aligned.m8n8.x4.trans.shared.b16 {%0,%1,%2,%3},[%4];"
                 : "=r"(r[0]), "=r"(r[1]), "=r"(r[2]), "=r"(r[3]) : "r"(a));
}
__device__ __forceinline__ void mma16816(float* c, const uint32_t* a, const uint32_t* b) {
    asm volatile("mma.sync.aligned.m16n8k16.row.col.f32.bf16.bf16.f32 "
                 "{%0,%1,%2,%3},{%4,%5,%6,%7},{%8,%9},{%0,%1,%2,%3};"
                 : "+f"(c[0]), "+f"(c[1]), "+f"(c[2]), "+f"(c[3])
                 : "r"(a[0]), "r"(a[1]), "r"(a[2]), "r"(a[3]), "r"(b[0]), "r"(b[1]));
}
__device__ __forceinline__ void cpa16(void* s, const void* g) {
    asm volatile("cp.async.cg.shared.global [%0],[%1],16;" :: "r"(cvta_s(s)), "l"(g));
}
#define CP_COMMIT asm volatile("cp.async.commit_group;")
#define CP_WAIT0  asm volatile("cp.async.wait_group 0;")
#define CP_WAIT2  asm volatile("cp.async.wait_group 2;")

__device__ __forceinline__ uint2 f4b(float4 v) {
    __nv_bfloat162 lo, hi;
    lo.x = __float2bfloat16(v.x); lo.y = __float2bfloat16(v.y);
    hi.x = __float2bfloat16(v.z); hi.y = __float2bfloat16(v.w);
    uint2 r;
    r.x = *(uint32_t*)&lo;
    r.y = *(uint32_t*)&hi;
    return r;
}

// ---------------------------------------------------------------------------
// proj mma (merged z=5) — VERBATIM R14
// ---------------------------------------------------------------------------
__global__ __launch_bounds__(256) void proj_mma_f32(
    const float* __restrict__ x_in, const float* __restrict__ g_in,
    const float* __restrict__ Wx1, const float* __restrict__ bx1,
    const float* __restrict__ Wx2, const float* __restrict__ bx2,
    const float* __restrict__ Wx3, const float* __restrict__ bx3,
    const float* __restrict__ Wg1, const float* __restrict__ bg1,
    const float* __restrict__ Wg2, const float* __restrict__ bg2)
{
    __shared__ __align__(16) __nv_bfloat16 As[2][128][40];
    __shared__ __align__(16) __nv_bfloat16 Ws[2][32][136];
    const int z = blockIdx.z;
    const float* A; const float* W; const float* bias; int wantf32;
    if (z == 0)      { A = x_in; W = Wx1; bias = bx1; wantf32 = 0; }
    else if (z == 1) { A = x_in; W = Wx2; bias = bx2; wantf32 = 0; }
    else if (z == 2) { A = x_in; W = Wx3; bias = bx3; wantf32 = 1; }
    else if (z == 3) { A = g_in; W = Wg1; bias = bg1; wantf32 = 0; }
    else             { A = g_in; W = Wg2; bias = bg2; wantf32 = 0; }

    const int tid = threadIdx.x, lane = tid & 31, wid = tid >> 5;
    const int wm = wid & 1, wn = wid >> 1;
    const int m0 = blockIdx.y * 128, n0 = blockIdx.x * 128;
    __nv_bfloat16* Dst = g_Pb + (size_t)z * PROJ_SZ;

    const int arow = tid >> 1;
    const int ak   = (tid & 1) * 16;
    const int wrow = tid >> 3;
    const int wn16 = (tid & 7) * 16;

    float4 ra0, ra1, ra2, ra3, rw0, rw1, rw2, rw3;
    {
        const float* ap = A + (size_t)(m0 + arow) * CH + ak;
        ra0 = *(const float4*)(ap + 0);  ra1 = *(const float4*)(ap + 4);
        ra2 = *(const float4*)(ap + 8);  ra3 = *(const float4*)(ap + 12);
        const float* wp = W + (size_t)wrow * CH + n0 + wn16;
        rw0 = *(const float4*)(wp + 0);  rw1 = *(const float4*)(wp + 4);
        rw2 = *(const float4*)(wp + 8);  rw3 = *(const float4*)(wp + 12);
    }
    *(uint2*)&As[0][arow][ak + 0]  = f4b(ra0);
    *(uint2*)&As[0][arow][ak + 4]  = f4b(ra1);
    *(uint2*)&As[0][arow][ak + 8]  = f4b(ra2);
    *(uint2*)&As[0][arow][ak + 12] = f4b(ra3);
    *(uint2*)&Ws[0][wrow][wn16 + 0]  = f4b(rw0);
    *(uint2*)&Ws[0][wrow][wn16 + 4]  = f4b(rw1);
    *(uint2*)&Ws[0][wrow][wn16 + 8]  = f4b(rw2);
    *(uint2*)&Ws[0][wrow][wn16 + 12] = f4b(rw3);
    __syncthreads();

    float acc[4][4][4] = {};
#pragma unroll 1
    for (int s = 0; s < 8; s++) {
        if (s < 7) {
            const int k0 = (s + 1) * 32;
            const float* ap = A + (size_t)(m0 + arow) * CH + k0 + ak;
            ra0 = *(const float4*)(ap + 0);  ra1 = *(const float4*)(ap + 4);
            ra2 = *(const float4*)(ap + 8);  ra3 = *(const float4*)(ap + 12);
            const float* wp = W + (size_t)(k0 + wrow) * CH + n0 + wn16;
            rw0 = *(const float4*)(wp + 0);  rw1 = *(const float4*)(wp + 4);
            rw2 = *(const float4*)(wp + 8);  rw3 = *(const float4*)(wp + 12);
        }
        const int st = s & 1;
#pragma unroll
        for (int kk = 0; kk < 2; kk++) {
            uint32_t a[4][4], b[4][2];
#pragma unroll
            for (int mf = 0; mf < 4; mf++) {
                const int row = wm * 64 + mf * 16 + (lane & 15);
                const int ko = kk * 16 + (lane >> 4) * 8;
                ldsm4(a[mf], cvta_s(&As[st][row][ko]));
            }
#pragma unroll
            for (int np = 0; np < 2; np++) {
                const int row = kk * 16 + (lane & 7) + ((lane >> 3) & 1) * 8;
                const int col = wn * 32 + np * 16 + (lane >> 4) * 8;
                uint32_t r[4];
                ldsm4t(r, cvta_s(&Ws[st][row][col]));
                b[2 * np][0] = r[0]; b[2 * np][1] = r[1];
                b[2 * np + 1][0] = r[2]; b[2 * np + 1][1] = r[3];
            }
#pragma unroll
            for (int mf = 0; mf < 4; mf++)
#pragma unroll
                for (int nf = 0; nf < 4; nf++) mma16816(acc[mf][nf], a[mf], b[nf]);
        }
        __syncthreads();
        if (s < 7) {
            const int st2 = (s + 1) & 1;
            *(uint2*)&As[st2][arow][ak + 0]  = f4b(ra0);
            *(uint2*)&As[st2][arow][ak + 4]  = f4b(ra1);
            *(uint2*)&As[st2][arow][ak + 8]  = f4b(ra2);
            *(uint2*)&As[st2][arow][ak + 12] = f4b(ra3);
            *(uint2*)&Ws[st2][wrow][wn16 + 0]  = f4b(rw0);
            *(uint2*)&Ws[st2][wrow][wn16 + 4]  = f4b(rw1);
            *(uint2*)&Ws[st2][wrow][wn16 + 8]  = f4b(rw2);
            *(uint2*)&Ws[st2][wrow][wn16 + 12] = f4b(rw3);
            __syncthreads();
        }
    }

    const int mm0 = m0 + wm * 64, nn0 = n0 + wn * 32;
#pragma unroll
    for (int mf = 0; mf < 4; mf++) {
        const int r0 = mm0 + mf * 16 + (lane >> 2);
#pragma unroll
        for (int nf = 0; nf < 4; nf++) {
            const int col = nn0 + nf * 8 + (lane & 3) * 2;
            const float b0 = bias[col], b1 = bias[col + 1];
            const float f0 = acc[mf][nf][0] + b0, f1 = acc[mf][nf][1] + b1;
            const float f2 = acc[mf][nf][2] + b0, f3 = acc[mf][nf][3] + b1;
            __nv_bfloat162 v0, v1;
            v0.x = __float2bfloat16(f0); v0.y = __float2bfloat16(f1);
            v1.x = __float2bfloat16(f2); v1.y = __float2bfloat16(f3);
            *(__nv_bfloat162*)&Dst[(size_t)r0 * CH + col] = v0;
            *(__nv_bfloat162*)&Dst[(size_t)(r0 + 8) * CH + col] = v1;
            if (wantf32) {
                float2 w0; w0.x = f0; w0.y = f1;
                float2 w1; w1.x = f2; w1.y = f3;
                *(float2*)&g_X3[(size_t)r0 * CH + col] = w0;
                *(float2*)&g_X3[(size_t)(r0 + 8) * CH + col] = w1;
            }
        }
    }
}

// ---------------------------------------------------------------------------
// score_ms — R14 pipeline; epilogue now stores E = exp(S) (MUFU overlapped
// into the tensor-bound kernel; removes all exps from row_stats)
// ---------------------------------------------------------------------------
#define SC_TILE 5120   // 128 rows * 40 elems per stage

__global__ __launch_bounds__(256) void score_ms() {
    extern __shared__ __align__(16) __nv_bfloat16 sm[];
    __nv_bfloat16* Asm = sm;
    __nv_bfloat16* Bsm = sm + 4 * SC_TILE;
    const int tid = threadIdx.x, lane = tid & 31, wid = tid >> 5;
    const int wm = wid & 1, wn = wid >> 1;
    const int lrow = tid >> 1, lch = (tid & 1) * 2;
    const int z = blockIdx.z, bat = z >> 1, branch = z & 1;
    const __nv_bfloat16* A  = g_Pb + (size_t)(branch ? 4 : 1) * PROJ_SZ
                              + (size_t)bat * HW * CH + (size_t)blockIdx.y * 128 * CH;
    const __nv_bfloat16* Bm = g_Pb + (size_t)(branch ? 3 : 0) * PROJ_SZ
                              + (size_t)bat * HW * CH + (size_t)blockIdx.x * 128 * CH;
    __nv_bfloat16* Dst = (branch ? g_Eg : g_Ex) + (size_t)bat * HW * HW;

#pragma unroll
    for (int s = 0; s < 3; s++) {
        const int k0 = s * 32;
        __nv_bfloat16* Ad = Asm + s * SC_TILE;
        __nv_bfloat16* Bd = Bsm + s * SC_TILE;
#pragma unroll
        for (int q = 0; q < 2; q++) {
            cpa16(&Ad[lrow * 40 + (lch + q) * 8], A + (size_t)lrow * CH + k0 + (lch + q) * 8);
            cpa16(&Bd[lrow * 40 + (lch + q) * 8], Bm + (size_t)lrow * CH + k0 + (lch + q) * 8);
        }
        CP_COMMIT;
    }

    float acc[4][4][4] = {};
#pragma unroll 1
    for (int s = 0; s < 8; s++) {
        CP_WAIT2;
        __syncthreads();
        const int st = s & 3;
        const __nv_bfloat16* Ap = Asm + st * SC_TILE;
        const __nv_bfloat16* Bp = Bsm + st * SC_TILE;
#pragma unroll
        for (int kk = 0; kk < 2; kk++) {
            uint32_t a[4][4], b[4][2];
#pragma unroll
            for (int mf = 0; mf < 4; mf++) {
                const int row = wm * 64 + mf * 16 + (lane & 15);
                const int ko = kk * 16 + (lane >> 4) * 8;
                ldsm4(a[mf], cvta_s(&Ap[row * 40 + ko]));
            }
#pragma unroll
            for (int np = 0; np < 2; np++) {
                const int row = wn * 32 + np * 16 + (lane & 7) + (lane >> 4) * 8;
                const int ko = kk * 16 + ((lane >> 3) & 1) * 8;
                uint32_t r[4];
                ldsm4(r, cvta_s(&Bp[row * 40 + ko]));
                b[2 * np][0] = r[0]; b[2 * np][1] = r[1];
                b[2 * np + 1][0] = r[2]; b[2 * np + 1][1] = r[3];
            }
#pragma unroll
            for (int mf = 0; mf < 4; mf++)
#pragma unroll
                for (int nf = 0; nf < 4; nf++) mma16816(acc[mf][nf], a[mf], b[nf]);
        }
        if (s < 5) {
            const int k0 = (s + 3) * 32, st2 = (s + 3) & 3;
            __nv_bfloat16* Ad = Asm + st2 * SC_TILE;
            __nv_bfloat16* Bd = Bsm + st2 * SC_TILE;
#pragma unroll
            for (int q = 0; q < 2; q++) {
                cpa16(&Ad[lrow * 40 + (lch + q) * 8],
                      A + (size_t)lrow * CH + k0 + (lch + q) * 8);
                cpa16(&Bd[lrow * 40 + (lch + q) * 8],
                      Bm + (size_t)lrow * CH + k0 + (lch + q) * 8);
            }
        }
        CP_COMMIT;
    }

    const int m0 = blockIdx.y * 128 + wm * 64, n0 = blockIdx.x * 128 + wn * 32;
#pragma unroll
    for (int mf = 0; mf < 4; mf++) {
        const int r0 = m0 + mf * 16 + (lane >> 2);
#pragma unroll
        for (int nf = 0; nf < 4; nf++) {
            const int col = n0 + nf * 8 + (lane & 3) * 2;
            __nv_bfloat162 v0, v1;
            v0.x = __float2bfloat16(__expf(acc[mf][nf][0]));
            v0.y = __float2bfloat16(__expf(acc[mf][nf][1]));
            v1.x = __float2bfloat16(__expf(acc[mf][nf][2]));
            v1.y = __float2bfloat16(__expf(acc[mf][nf][3]));
            *(__nv_bfloat162*)&Dst[(size_t)r0 * HW + col] = v0;
            *(__nv_bfloat162*)&Dst[(size_t)(r0 + 8) * HW + col] = v1;
        }
    }
}
#define SC_SMEM_BYTES (8 * SC_TILE * 2)   // 81920

// ---------------------------------------------------------------------------
// row stats — 256 threads (R14 shape), NO exps: reads E = exp(S) directly
// ---------------------------------------------------------------------------
__device__ __forceinline__ float blk_sum(float v, float* red) {
    int tid = threadIdx.x;
    red[tid] = v; __syncthreads();
    for (int s = 128; s > 0; s >>= 1) {
        if (tid < s) red[tid] += red[tid + s];
        __syncthreads();
    }
    float r = red[0]; __syncthreads();
    return r;
}

__global__ void row_stats_kernel() {
    __shared__ float prod[HW];
    __shared__ float red[256];
    const int row = blockIdx.x;
    const int tid = threadIdx.x;
    const __nv_bfloat16* px = g_Ex + (size_t)row * HW;
    const __nv_bfloat16* pg = g_Eg + (size_t)row * HW;

    float s1 = 0.f, s2 = 0.f;
    for (int t = tid; t < HW / 4; t += 256) {
        __nv_bfloat162 x0 = *(const __nv_bfloat162*)&px[t * 4];
        __nv_bfloat162 x1 = *(const __nv_bfloat162*)&px[t * 4 + 2];
        __nv_bfloat162 g0 = *(const __nv_bfloat162*)&pg[t * 4];
        __nv_bfloat162 g1 = *(const __nv_bfloat162*)&pg[t * 4 + 2];
        const float ex0 = __bfloat162float(x0.x);
        const float ex1 = __bfloat162float(x0.y);
        const float ex2 = __bfloat162float(x1.x);
        const float ex3 = __bfloat162float(x1.y);
        const float eg0 = __bfloat162float(g0.x);
        const float eg1 = __bfloat162float(g0.y);
        const float eg2 = __bfloat162float(g1.x);
        const float eg3 = __bfloat162float(g1.y);
        s1 += ex0 + ex1 + ex2 + ex3;
        s2 += eg0 + eg1 + eg2 + eg3;
        prod[t * 4 + 0] = ex0 * eg0;
        prod[t * 4 + 1] = ex1 * eg1;
        prod[t * 4 + 2] = ex2 * eg2;
        prod[t * 4 + 3] = ex3 * eg3;
    }
    __syncthreads();
    const float Zx = blk_sum(s1, red);
    const float Zg = blk_sum(s2, red);
    const float invZZ = 1.f / (Zx * Zg);

    __nv_bfloat16* vo = g_V + (size_t)row * HW;
    float s = 0.f;
    for (int t = tid; t < HW; t += 256) {
        const float p = prod[t] * invZZ;
        const float vv = p * (1.f + p * (0.5f + p * (0.16666667f
                         + p * (0.04166667f + p * 0.00833333f))));
        s += vv;
        vo[t] = __float2bfloat16(vv);
    }
    const float Z2 = (float)HW + blk_sum(s, red);
    if (tid == 0) g_invZ2[row] = 1.f / Z2;
}

// ---------------------------------------------------------------------------
// fold + colsum — VERBATIM R14
// ---------------------------------------------------------------------------
__global__ void fold_kernel() {
    const int blk = blockIdx.x;
    const int bat = blk >> 9;
    const int i0 = (blk & 511) * 8;
    const int c = threadIdx.x;
    const float* X = g_X3 + ((size_t)bat * HW + i0) * CH;
    __nv_bfloat16* P = g_X3p + ((size_t)bat * HW + i0) * CH;
    const float* iz = g_invZ2 + bat * HW + i0;
    float s = 0.f;
#pragma unroll
    for (int r = 0; r < 8; r++) {
        const float val = X[(size_t)r * CH + c] * iz[r];
        s += val;
        P[(size_t)r * CH + c] = __float2bfloat16(val);
    }
    g_colpart[blk * CH + c] = s;
}
__global__ void colsum_stage1() {
    const int blk = blockIdx.x;
    const int c = threadIdx.x;
    float s = 0.f;
#pragma unroll 4
    for (int k = 0; k < 16; k++) s += g_colpart[(blk * 16 + k) * CH + c];
    g_colpart2[blk * CH + c] = s;
}
__global__ void colsum_reduce() {
    const int bat = blockIdx.x, c = threadIdx.x;
    float s = 0.f;
#pragma unroll
    for (int k = 0; k < 32; k++) s += g_colpart2[(bat * 32 + k) * CH + c];
    g_colsum[bat * CH + c] = s;
}

// ---------------------------------------------------------------------------
// out_ms — VERBATIM R14 (4-stage cp.async ring, 128x128 tile)
// ---------------------------------------------------------------------------
#define OT_TILE 4352   // 32 * 136

__global__ __launch_bounds__(256) void out_ms(const float* __restrict__ x_in,
                                              float* __restrict__ out) {
    extern __shared__ __align__(16) __nv_bfloat16 osm[];
    __nv_bfloat16* Vsm = osm;
    __nv_bfloat16* Xsm = osm + 4 * OT_TILE;
    __shared__ float cs_s[128];
    const int bat = blockIdx.z;
    const int j0 = blockIdx.y * 128, c0 = blockIdx.x * 128;
    const __nv_bfloat16* V = g_V + (size_t)bat * HW * HW;      // [i][j]
    const __nv_bfloat16* X = g_X3p + (size_t)bat * HW * CH;    // [i][c]
    const int tid = threadIdx.x, lane = tid & 31, wid = tid >> 5;
    const int wm = wid & 1, wn = wid >> 1;
    const int vrow = tid >> 3;          // 0..31
    const int vch = (tid & 7) * 2;

    if (tid < 128) cs_s[tid] = g_colsum[bat * CH + c0 + tid];

    // prefetch stages 0..2
#pragma unroll
    for (int s = 0; s < 3; s++) {
        const int i0 = s * 32;
        __nv_bfloat16* Vd = Vsm + s * OT_TILE;
        __nv_bfloat16* Xd = Xsm + s * OT_TILE;
#pragma unroll
        for (int q = 0; q < 2; q++) {
            cpa16(&Vd[vrow * 136 + (vch + q) * 8],
                  V + (size_t)(i0 + vrow) * HW + j0 + (vch + q) * 8);
            cpa16(&Xd[vrow * 136 + (vch + q) * 8],
                  X + (size_t)(i0 + vrow) * CH + c0 + (vch + q) * 8);
        }
        CP_COMMIT;
    }

    float acc[4][4][4] = {};
#pragma unroll 1
    for (int s = 0; s < 128; s++) {
        CP_WAIT2;
        __syncthreads();
        const int st = s & 3;
        const __nv_bfloat16* Vp = Vsm + st * OT_TILE;
        const __nv_bfloat16* Xp = Xsm + st * OT_TILE;
#pragma unroll
        for (int kk = 0; kk < 2; kk++) {
            uint32_t a[4][4], b[4][2];
#pragma unroll
            for (int mf = 0; mf < 4; mf++) {
                const int row = kk * 16 + (lane & 7) + (lane >> 4) * 8;
                const int col = wm * 64 + mf * 16 + ((lane >> 3) & 1) * 8;
                ldsm4t(a[mf], cvta_s(&Vp[row * 136 + col]));
            }
#pragma unroll
            for (int np = 0; np < 2; np++) {
                const int row = kk * 16 + (lane & 7) + ((lane >> 3) & 1) * 8;
                const int col = wn * 32 + np * 16 + (lane >> 4) * 8;
                uint32_t r[4];
                ldsm4t(r, cvta_s(&Xp[row * 136 + col]));
                b[2 * np][0] = r[0]; b[2 * np][1] = r[1];
                b[2 * np + 1][0] = r[2]; b[2 * np + 1][1] = r[3];
            }
#pragma unroll
            for (int mf = 0; mf < 4; mf++)
#pragma unroll
                for (int nf = 0; nf < 4; nf++) mma16816(acc[mf][nf], a[mf], b[nf]);
        }
        if (s < 125) {
            const int i0 = (s + 3) * 32, st2 = (s + 3) & 3;
            __nv_bfloat16* Vd = Vsm + st2 * OT_TILE;
            __nv_bfloat16* Xd = Xsm + st2 * OT_TILE;
#pragma unroll
            for (int q = 0; q < 2; q++) {
                cpa16(&Vd[vrow * 136 + (vch + q) * 8],
                      V + (size_t)(i0 + vrow) * HW + j0 + (vch + q) * 8);
                cpa16(&Xd[vrow * 136 + (vch + q) * 8],
                      X + (size_t)(i0 + vrow) * CH + c0 + (vch + q) * 8);
            }
        }
        CP_COMMIT;
    }

#pragma unroll
    for (int mf = 0; mf < 4; mf++) {
        const int j = j0 + wm * 64 + mf * 16 + (lane >> 2);
#pragma unroll
        for (int nf = 0; nf < 4; nf++) {
            const int cc = wn * 32 + nf * 8 + (lane & 3) * 2;
            const size_t b0 = ((size_t)bat * HW + j) * CH + c0 + cc;
            float2 xv = *(const float2*)&x_in[b0];
            float2 o;
            o.x = acc[mf][nf][0] + xv.x + cs_s[cc];
            o.y = acc[mf][nf][1] + xv.y + cs_s[cc + 1];
            *(float2*)&out[b0] = o;
            const size_t b1 = ((size_t)bat * HW + j + 8) * CH + c0 + cc;
            float2 xv2 = *(const float2*)&x_in[b1];
            float2 o2;
            o2.x = acc[mf][nf][2] + xv2.x + cs_s[cc];
            o2.y = acc[mf][nf][3] + xv2.y + cs_s[cc + 1];
            *(float2*)&out[b1] = o2;
        }
    }
}
#define OT_SMEM_BYTES (8 * OT_TILE * 2)   // 69632

// ---------------------------------------------------------------------------
extern "C" void kernel_launch(void* const* d_in, const int* in_sizes, int n_in,
                              void* d_out, int out_size) {
    (void)in_sizes; (void)n_in; (void)out_size;
    const float* x   = (const float*)d_in[0];
    const float* g   = (const float*)d_in[1];
    float* out = (float*)d_out;

    dim3 pg(CH / 128, (BATCH * HW) / 128, 5);
    proj_mma_f32<<<pg, 256>>>(x, g,
        (const float*)d_in[2],  (const float*)d_in[3],
        (const float*)d_in[4],  (const float*)d_in[5],
        (const float*)d_in[6],  (const float*)d_in[7],
        (const float*)d_in[8],  (const float*)d_in[9],
        (const float*)d_in[10], (const float*)d_in[11]);

    cudaFuncSetAttribute(score_ms, cudaFuncAttributeMaxDynamicSharedMemorySize,
                         SC_SMEM_BYTES);
    score_ms<<<dim3(32, 32, 8), 256, SC_SMEM_BYTES>>>();

    row_stats_kernel<<<BATCH * HW, 256>>>();
    fold_kernel<<<2048, 256>>>();
    colsum_stage1<<<128, 256>>>();
    colsum_reduce<<<BATCH, 256>>>();

    cudaFuncSetAttribute(out_ms, cudaFuncAttributeMaxDynamicSharedMemorySize,
                         OT_SMEM_BYTES);
    out_ms<<<dim3(CH / 128, HW / 128, BATCH), 256, OT_SMEM_BYTES>>>(x, out);
}